// round 17
// baseline (speedup 1.0000x reference)
#include <cuda_runtime.h>
#include <cuda_bf16.h>
#include <math_constants.h>

// CRF neg-log-likelihood, GB300 sm_103a.
// 64 CTAs x 64 threads (2 warps). REDUNDANT-WARP design: each warp computes
// the full 50-tag GEMV for the SAME row into its own private smem buffer ->
// no cross-warp dependency -> __syncwarp instead of __syncthreads in the loop.
// Lane l<25 owns columns (2l,2l+1); accumulator pair IS the output pair (no
// horizontal reduce). Partition stored SPLATTED (word i=(p_i,p_i): 2 PRMT +
// STS.64 at production; 13 LDS.128 + 26 HFMA2 at consumption, zero PRMTs).
// exp(feats) precomputed to smem as bf162 pairs. Rescale by p[0] every 4
// steps. Mask fast path. Gold score + batch reduce as before.

namespace {
constexpr int NTAG   = 50;
constexpr int TSTART = NTAG - 2;   // 48
constexpr int TSTOP  = NTAG - 1;   // 49
constexpr int BATCH  = 64;
constexpr int SEQ    = 512;
constexpr int NTHR   = 64;
constexpr int NW     = 52;         // splatted partition words (50 + 2 zero pad)
constexpr int EFP    = 25;         // ef pair-words per step
constexpr int SMEM_EF_WORDS = SEQ * EFP;     // 51.2 KB
constexpr int SMEM_BYTES    = (SMEM_EF_WORDS + SEQ + 1) * 4;
}

__device__ float    g_partial[BATCH];
__device__ unsigned g_ticket = 0;

__device__ __forceinline__ float warpSumF(float v) {
#pragma unroll
    for (int o = 16; o > 0; o >>= 1) v += __shfl_xor_sync(0xffffffffu, v, o);
    return v;
}
__device__ __forceinline__ int warpSumI(int v) {
#pragma unroll
    for (int o = 16; o > 0; o >>= 1) v += __shfl_xor_sync(0xffffffffu, v, o);
    return v;
}
__device__ __forceinline__ __nv_bfloat162 asbf2(float f) {
    return *reinterpret_cast<__nv_bfloat162*>(&f);
}
__device__ __forceinline__ __nv_bfloat162 u2b(unsigned u) {
    return *reinterpret_cast<__nv_bfloat162*>(&u);
}
__device__ __forceinline__ unsigned b2u(__nv_bfloat162 b) {
    return *reinterpret_cast<unsigned*>(&b);
}
__device__ __forceinline__ unsigned splat_lo(unsigned a) {
    unsigned r; asm("prmt.b32 %0, %1, 0, 0x1010;" : "=r"(r) : "r"(a)); return r;
}
__device__ __forceinline__ unsigned splat_hi(unsigned a) {
    unsigned r; asm("prmt.b32 %0, %1, 0, 0x3232;" : "=r"(r) : "r"(a)); return r;
}

// GEMV: 13 LDS.128 over the 52 splatted words; 26 HFMA2 into 8 accumulators.
// Result pair = (q_2l, q_2l+1). Exports p0 as fp32 (word 0 = (p0,p0)).
__device__ __forceinline__ __nv_bfloat162 gemv52(
    const unsigned* __restrict__ src,
    const __nv_bfloat162 (&et2)[NW],
    float& p0f)
{
    const float4* s4 = (const float4*)src;
    float4 v[13];
#pragma unroll
    for (int q = 0; q < 13; q++) v[q] = s4[q];

    p0f = __uint_as_float(__float_as_uint(v[0].x) << 16);

    __nv_bfloat162 z = __floats2bfloat162_rn(0.f, 0.f);
    __nv_bfloat162 a[8];
#pragma unroll
    for (int i = 0; i < 8; i++) a[i] = z;

#pragma unroll
    for (int q = 0; q < 13; q++) {
        a[(4 * q + 0) & 7] = __hfma2(asbf2(v[q].x), et2[4 * q + 0], a[(4 * q + 0) & 7]);
        a[(4 * q + 1) & 7] = __hfma2(asbf2(v[q].y), et2[4 * q + 1], a[(4 * q + 1) & 7]);
        a[(4 * q + 2) & 7] = __hfma2(asbf2(v[q].z), et2[4 * q + 2], a[(4 * q + 2) & 7]);
        a[(4 * q + 3) & 7] = __hfma2(asbf2(v[q].w), et2[4 * q + 3], a[(4 * q + 3) & 7]);
    }

    a[0] = __hadd2(a[0], a[4]);
    a[1] = __hadd2(a[1], a[5]);
    a[2] = __hadd2(a[2], a[6]);
    a[3] = __hadd2(a[3], a[7]);
    a[0] = __hadd2(a[0], a[1]);
    a[2] = __hadd2(a[2], a[3]);
    return __hadd2(a[0], a[2]);
}

// FAST step (mask==1). src/dst are THIS warp's private buffers.
template <bool RESCALE>
__device__ __forceinline__ void step_fast(
    int t, int l, bool act, int lc,
    const unsigned* __restrict__ src,
    unsigned*       __restrict__ dst,
    const __nv_bfloat162 (&et2)[NW],
    unsigned& efp, float& offset,
    const unsigned* __restrict__ s_ef)
{
    float p0f;
    __nv_bfloat162 s2 = gemv52(src, et2, p0f);
    float rp0 = 1.f;
    if (RESCALE) rp0 = __frcp_rn(p0f);

    __nv_bfloat162 q2 = __hmul2(s2, u2b(efp));   // * (ef_2l, ef_2l+1)
    if (RESCALE) q2 = __hmul2(q2, __float2bfloat162_rn(rp0));

    if (act) {
        unsigned qu = b2u(q2);
        uint2 st;
        st.x = splat_lo(qu);                      // (q_2l,  q_2l)
        st.y = splat_hi(qu);                      // (q_2l+1,q_2l+1)
        *(uint2*)(dst + 2 * l) = st;              // STS.64
    }

    efp = s_ef[(t + 1) * EFP + lc];               // off-path prefetch
    if (RESCALE) offset += __logf(p0f);

    __syncwarp();                                  // warp-private exchange
}

// GENERAL step: honors mask.
template <bool RESCALE>
__device__ __forceinline__ void step_gen(
    int t, int l, bool act, int lc,
    const unsigned* __restrict__ src,
    unsigned*       __restrict__ dst,
    const __nv_bfloat162 (&et2)[NW],
    unsigned& efp, unsigned& pju, float& offset, int& m,
    const unsigned* __restrict__ s_ef,
    const int*      __restrict__ s_mask)
{
    float p0f;
    __nv_bfloat162 s2 = gemv52(src, et2, p0f);
    float rp0 = 1.f;
    if (RESCALE) rp0 = __frcp_rn(p0f);

    unsigned q2u = b2u(__hmul2(s2, u2b(efp)));
    q2u = m ? q2u : pju;
    if (RESCALE) q2u = b2u(__hmul2(u2b(q2u), __float2bfloat162_rn(rp0)));
    pju = q2u;

    if (act) {
        uint2 st;
        st.x = splat_lo(q2u);
        st.y = splat_hi(q2u);
        *(uint2*)(dst + 2 * l) = st;
    }

    efp = s_ef[(t + 1) * EFP + lc];
    m   = s_mask[t + 1];
    if (RESCALE) offset += __logf(p0f);

    __syncwarp();
}

__global__ void __launch_bounds__(NTHR, 1)
crf_kernel(const float* __restrict__ feats,
           const int*   __restrict__ mask,
           const int*   __restrict__ tags,
           const float* __restrict__ trans,
           float*       __restrict__ out)
{
    const int b    = blockIdx.x;
    const int j    = threadIdx.x;
    const int lane = j & 31;
    const int wid  = j >> 5;
    const bool act = (lane < EFP);        // lane owns columns (2l, 2l+1)
    const int lc   = act ? lane : EFP - 1;

    extern __shared__ unsigned dyn[];
    unsigned* s_ef   = dyn;                          // [SEQ][25] ef pairs
    int*      s_mask = (int*)(dyn + SMEM_EF_WORDS);  // [SEQ+1]

    __shared__ __align__(16) unsigned sp[2][2][NW + 4];  // [warp][pp][52+pad]
    __shared__ float s_fwd;
    __shared__ float s_acc[2];
    __shared__ int   s_len[2];
    __shared__ int   s_ones[2];
    __shared__ bool  s_last;
    __shared__ float s_red2[2];

    const float* fb = feats + (long long)b * SEQ * NTAG;
    const int*   mb = mask  + b * SEQ;
    const int*   tb = tags  + b * SEQ;

    // ---- prologue: mask + all-ones count + ef pairs ----
    {
        int cnt = 0;
        for (int t = j; t < SEQ; t += NTHR) { int v = mb[t]; s_mask[t] = v; cnt += v; }
        cnt = warpSumI(cnt);
        if (lane == 0) s_ones[wid] = cnt;
        if (j == 0) s_mask[SEQ] = 0;
    }
#pragma unroll 4
    for (int idx = j; idx < SEQ * EFP; idx += NTHR) {
        int t = idx / EFP;
        int k = idx - t * EFP;
        float2 fv = *(const float2*)(fb + t * NTAG + 2 * k);
        s_ef[idx] = b2u(__floats2bfloat162_rn(__expf(fv.x), __expf(fv.y)));
    }

    // exp(transitions) for this lane's column pair: et2[i] = (E[i][2l], E[i][2l+1])
    __nv_bfloat162 et2[NW];
    et2[50] = __floats2bfloat162_rn(0.f, 0.f);
    et2[51] = et2[50];
    if (act) {
#pragma unroll
        for (int i = 0; i < NTAG; i++) {
            float e0 = __expf(trans[i * NTAG + 2 * lc]);
            float e1 = __expf(trans[i * NTAG + 2 * lc + 1]);
            et2[i] = __floats2bfloat162_rn(e0, e1);
        }
    } else {
#pragma unroll
        for (int i = 0; i < NTAG; i++) et2[i] = __floats2bfloat162_rn(0.f, 0.f);
    }

    // t = 0: normalize by partition0[tag 0]; fill own warp's buffer
    unsigned* bufA = sp[wid][0];
    unsigned* bufB = sp[wid][1];
    const float off0   = fb[0] + trans[TSTART * NTAG + 0];
    float       offset = off0;
    float2 f0 = *(const float2*)(fb + 2 * lc);
    float pa = __expf(f0.x + trans[TSTART * NTAG + 2 * lc]     - off0);
    float pb = __expf(f0.y + trans[TSTART * NTAG + 2 * lc + 1] - off0);
    unsigned pju = b2u(__floats2bfloat162_rn(pa, pb));
    if (act) {
        uint2 st;
        st.x = splat_lo(pju);
        st.y = splat_hi(pju);
        *(uint2*)(bufA + 2 * lane) = st;
    }
    if (lane >= 2 * EFP && lane < NW + 4 && lane - 0 < NW + 4) { }  // no-op
    // zero pads (words 50,51 + spare) in both buffers
    if (lane < 6) { bufA[NW - 2 + lane] = 0u; bufB[NW - 2 + lane] = 0u; }
    __syncthreads();   // covers prologue smem writes (ef/mask shared by warps)

    const bool allOnes = (s_ones[0] + s_ones[1]) == SEQ;
    unsigned efp = s_ef[1 * EFP + lc];

    if (allOnes) {
        for (int t = 1; t + 3 < SEQ; t += 4) {
            step_fast<false>(t,     lane, act, lc, bufA, bufB, et2, efp, offset, s_ef);
            step_fast<false>(t + 1, lane, act, lc, bufB, bufA, et2, efp, offset, s_ef);
            step_fast<false>(t + 2, lane, act, lc, bufA, bufB, et2, efp, offset, s_ef);
            step_fast<true >(t + 3, lane, act, lc, bufB, bufA, et2, efp, offset, s_ef);
        }
        step_fast<false>(SEQ - 3, lane, act, lc, bufA, bufB, et2, efp, offset, s_ef);
        step_fast<false>(SEQ - 2, lane, act, lc, bufB, bufA, et2, efp, offset, s_ef);
        {   // final step inline (no prefetch)
            float p0f;
            __nv_bfloat162 s2 = gemv52(bufA, et2, p0f);
            __nv_bfloat162 q2 = __hmul2(s2, u2b(efp));
            if (act) {
                unsigned qu = b2u(q2);
                uint2 st;
                st.x = splat_lo(qu);
                st.y = splat_hi(qu);
                *(uint2*)(bufB + 2 * lane) = st;
            }
            __syncwarp();
        }
    } else {
        int m = s_mask[1];
        for (int t = 1; t + 3 < SEQ; t += 4) {
            step_gen<false>(t,     lane, act, lc, bufA, bufB, et2, efp, pju, offset, m, s_ef, s_mask);
            step_gen<false>(t + 1, lane, act, lc, bufB, bufA, et2, efp, pju, offset, m, s_ef, s_mask);
            step_gen<false>(t + 2, lane, act, lc, bufA, bufB, et2, efp, pju, offset, m, s_ef, s_mask);
            step_gen<true >(t + 3, lane, act, lc, bufB, bufA, et2, efp, pju, offset, m, s_ef, s_mask);
        }
        step_gen<false>(SEQ - 3, lane, act, lc, bufA, bufB, et2, efp, pju, offset, m, s_ef, s_mask);
        step_gen<false>(SEQ - 2, lane, act, lc, bufB, bufA, et2, efp, pju, offset, m, s_ef, s_mask);
        {
            float p0f;
            __nv_bfloat162 s2 = gemv52(bufA, et2, p0f);
            unsigned q2u = b2u(__hmul2(s2, u2b(efp)));
            q2u = m ? q2u : pju;
            if (act) {
                uint2 st;
                st.x = splat_lo(q2u);
                st.y = splat_hi(q2u);
                *(uint2*)(bufB + 2 * lane) = st;
            }
            __syncwarp();
        }
    }
    // final partition (splatted) lives in bufB

    // terminal: s = P x exp(trans); column STOP = 49 = high half of lane 24.
    // Warp 0 computes and publishes.
    if (wid == 0) {
        float p0f;
        __nv_bfloat162 s2 = gemv52(bufB, et2, p0f);
        unsigned su = __shfl_sync(0xffffffffu, b2u(s2), 24);
        if (lane == 0) s_fwd = __logf(__high2float(u2b(su))) + offset;
    }

    // ---- gold score (both warps split the row) ----
    float acc = 0.f;
    int   len = 0;
#pragma unroll
    for (int t = j; t < SEQ; t += NTHR) {
        int tag  = tb[t];
        int prev = (t == 0) ? TSTART : tb[t - 1];
        int mm   = s_mask[t];
        if (mm) acc += fb[t * NTAG + tag] + trans[prev * NTAG + tag];
        len += mm;
    }
    acc = warpSumF(acc);
    len = warpSumI(len);
    if (lane == 0) { s_acc[wid] = acc; s_len[wid] = len; }
    __syncthreads();

    if (j == 0) {
        int   L     = s_len[0] + s_len[1];
        int   endid = tb[L - 1];
        float gold  = s_acc[0] + s_acc[1] + trans[endid * NTAG + TSTOP];
        g_partial[b] = s_fwd - gold;
        __threadfence();
        unsigned tk = atomicAdd(&g_ticket, 1u);
        s_last = (tk == BATCH - 1);
    }
    __syncthreads();

    // last CTA out: reduce the 64 batch values, reset ticket
    if (s_last) {
        float v = ((volatile float*)g_partial)[j];
        v = warpSumF(v);
        if (lane == 0) s_red2[wid] = v;
        __syncthreads();
        if (j == 0) {
            out[0] = s_red2[0] + s_red2[1];
            g_ticket = 0;
        }
    }
}

extern "C" void kernel_launch(void* const* d_in, const int* in_sizes, int n_in,
                              void* d_out, int out_size)
{
    const float* feats = (const float*)d_in[0];
    const int*   mask  = (const int*)d_in[1];
    const int*   tags  = (const int*)d_in[2];
    const float* trans = (const float*)d_in[3];
    float* out = (float*)d_out;

    cudaFuncSetAttribute(crf_kernel,
                         cudaFuncAttributeMaxDynamicSharedMemorySize, SMEM_BYTES);
    crf_kernel<<<BATCH, NTHR, SMEM_BYTES>>>(feats, mask, tags, trans, out);
}